// round 2
// baseline (speedup 1.0000x reference)
#include <cuda_runtime.h>
#include <cstddef>

#define N_NODES 50000
#define N_EDGES 800000

// ---------------- scratch (device globals: alloc-free rule) ----------------
__device__ float g_agg1[(size_t)N_NODES * 64];
__device__ float g_h1  [(size_t)N_NODES * 128];
__device__ float g_agg2[(size_t)N_NODES * 128];
__device__ int   g_is64;

// ---------------- helpers ----------------
__device__ __forceinline__ void red_add_v4(float* p, float4 v) {
    asm volatile("red.global.add.v4.f32 [%0], {%1, %2, %3, %4};"
                 :: "l"(p), "f"(v.x), "f"(v.y), "f"(v.z), "f"(v.w) : "memory");
}

// ---------------- dtype detection: int64 vs int32 edge_index ----------------
// If int64 (LE), every odd 32-bit word is the high half of a value < 50000 -> 0.
// If int32, odd words are random indices in [0,50000): P(all zero) ~ 2^-someting huge.
__global__ void detect_kernel(const unsigned int* __restrict__ p) {
    __shared__ int found;
    if (threadIdx.x == 0) found = 0;
    __syncthreads();
    for (int i = threadIdx.x; i < 4096; i += blockDim.x) {
        if (p[2 * i + 1] != 0u) found = 1;
    }
    __syncthreads();
    if (threadIdx.x == 0) g_is64 = found ? 0 : 1;
}

// ---------------- zero both aggregation buffers ----------------
__global__ void zero_kernel() {
    const float4 z = make_float4(0.f, 0.f, 0.f, 0.f);
    int stride = gridDim.x * blockDim.x;
    int idx = blockIdx.x * blockDim.x + threadIdx.x;
    const int n1 = N_NODES * 64 / 4;
    const int n2 = N_NODES * 128 / 4;
    float4* a1 = reinterpret_cast<float4*>(g_agg1);
    float4* a2 = reinterpret_cast<float4*>(g_agg2);
    for (int i = idx; i < n1; i += stride) a1[i] = z;
    for (int i = idx; i < n2; i += stride) a2[i] = z;
}

// ---------------- edge scatter-add (gather x[src], red-add to agg[dst]) ----
template <int C>
__global__ void __launch_bounds__(256)
scatter_kernel(const float* __restrict__ feat, float* __restrict__ agg,
               const void* __restrict__ ei) {
    const int per = C / 4;                      // float4s per edge row
    long long idx = (long long)blockIdx.x * blockDim.x + threadIdx.x;
    long long e  = idx / per;
    int c4 = (int)(idx % per) * 4;
    if (e >= N_EDGES) return;

    int src, dst;
    if (g_is64) {
        const long long* p = (const long long*)ei;
        src = (int)__ldg(p + e);
        dst = (int)__ldg(p + N_EDGES + e);
    } else {
        const int* p = (const int*)ei;
        src = __ldg(p + e);
        dst = __ldg(p + N_EDGES + e);
    }
    float4 v = *reinterpret_cast<const float4*>(feat + (size_t)src * C + c4);
    red_add_v4(agg + (size_t)dst * C + c4, v);
}

// ---------------- fused GIN MLP: h=(1+eps)x+agg; relu(h@Wa+ba)@Wb+bb -------
// Block: 256 threads = 16(tx: channels) x 16(ty: nodes); 64 nodes per block.
// Weights fully resident in dynamic smem. H must be 128.
template <int CIN, int H, int COUT, bool RELU_OUT>
__global__ void __launch_bounds__(256)
mlp_kernel(const float* __restrict__ x, const float* __restrict__ agg,
           const float* __restrict__ epsp,
           const float* __restrict__ Wa, const float* __restrict__ ba,
           const float* __restrict__ Wb, const float* __restrict__ bb,
           float* __restrict__ out) {
    extern __shared__ float s[];
    float* Was = s;                              // CIN*H
    float* Wbs = Was + CIN * H;                  // H*COUT
    float* bas = Wbs + H * COUT;                 // H
    float* bbs = bas + H;                        // COUT
    float* ins = bbs + COUT;                     // 64*(CIN+1)
    float* mid = ins + 64 * (CIN + 1);           // 64*(H+1)

    const int tid = threadIdx.x;

    // cooperative weight + bias load
    for (int i = tid; i < CIN * H / 4; i += 256)
        reinterpret_cast<float4*>(Was)[i] = reinterpret_cast<const float4*>(Wa)[i];
    for (int i = tid; i < H * COUT / 4; i += 256)
        reinterpret_cast<float4*>(Wbs)[i] = reinterpret_cast<const float4*>(Wb)[i];
    if (tid < H) bas[tid] = ba[tid];
    if (tid < COUT) bbs[tid] = bb[tid];

    const float epsf = 1.0f + __ldg(epsp);
    const int n0 = blockIdx.x * 64;

    // input tile: (1+eps)*x + agg, padded stride CIN+1
    for (int i = tid; i < 64 * CIN; i += 256) {
        int n = i / CIN, c = i - n * CIN;
        int gn = n0 + n;
        float v = 0.f;
        if (gn < N_NODES) {
            size_t g = (size_t)gn * CIN + c;
            v = epsf * x[g] + agg[g];
        }
        ins[n * (CIN + 1) + c] = v;
    }
    __syncthreads();

    const int tx = tid & 15;
    const int ty = tid >> 4;

    // ---- phase B: mid[64][H] = relu(ins @ Wa + ba), 4 nodes x 8 ch/thread
    {
        float acc[4][8];
        #pragma unroll
        for (int i = 0; i < 4; i++)
            #pragma unroll
            for (int j = 0; j < 8; j++) acc[i][j] = 0.f;

        #pragma unroll 4
        for (int k = 0; k < CIN; k++) {
            float a[4];
            #pragma unroll
            for (int i = 0; i < 4; i++) a[i] = ins[(ty * 4 + i) * (CIN + 1) + k];
            float4 w0 = *reinterpret_cast<float4*>(&Was[k * H + tx * 8]);
            float4 w1 = *reinterpret_cast<float4*>(&Was[k * H + tx * 8 + 4]);
            float w[8] = {w0.x, w0.y, w0.z, w0.w, w1.x, w1.y, w1.z, w1.w};
            #pragma unroll
            for (int i = 0; i < 4; i++)
                #pragma unroll
                for (int j = 0; j < 8; j++) acc[i][j] += a[i] * w[j];
        }
        #pragma unroll
        for (int i = 0; i < 4; i++)
            #pragma unroll
            for (int j = 0; j < 8; j++) {
                float v = acc[i][j] + bas[tx * 8 + j];
                mid[(ty * 4 + i) * (H + 1) + tx * 8 + j] = v > 0.f ? v : 0.f;
            }
    }
    __syncthreads();

    // ---- phase C: out = mid @ Wb + bb (optional relu), COUT/16 ch/thread
    {
        constexpr int CPT = COUT / 16;
        float acc[4][CPT];
        #pragma unroll
        for (int i = 0; i < 4; i++)
            #pragma unroll
            for (int j = 0; j < CPT; j++) acc[i][j] = 0.f;

        #pragma unroll 4
        for (int k = 0; k < H; k++) {
            float a[4];
            #pragma unroll
            for (int i = 0; i < 4; i++) a[i] = mid[(ty * 4 + i) * (H + 1) + k];
            float w[CPT];
            #pragma unroll
            for (int q = 0; q < CPT / 4; q++) {
                float4 wq = *reinterpret_cast<float4*>(&Wbs[k * COUT + tx * CPT + q * 4]);
                w[q * 4 + 0] = wq.x; w[q * 4 + 1] = wq.y;
                w[q * 4 + 2] = wq.z; w[q * 4 + 3] = wq.w;
            }
            #pragma unroll
            for (int i = 0; i < 4; i++)
                #pragma unroll
                for (int j = 0; j < CPT; j++) acc[i][j] += a[i] * w[j];
        }
        #pragma unroll
        for (int i = 0; i < 4; i++) {
            int gn = n0 + ty * 4 + i;
            if (gn < N_NODES) {
                #pragma unroll
                for (int j = 0; j < CPT; j++) {
                    float v = acc[i][j] + bbs[tx * CPT + j];
                    if (RELU_OUT) v = v > 0.f ? v : 0.f;
                    out[(size_t)gn * COUT + tx * CPT + j] = v;
                }
            }
        }
    }
}

// ---------------- launch ----------------
extern "C" void kernel_launch(void* const* d_in, const int* in_sizes, int n_in,
                              void* d_out, int out_size) {
    const float* x    = (const float*)d_in[0];
    const void*  ei   = d_in[1];
    const float* W1   = (const float*)d_in[2];
    const float* b1   = (const float*)d_in[3];
    const float* W2   = (const float*)d_in[4];
    const float* b2   = (const float*)d_in[5];
    const float* eps1 = (const float*)d_in[6];
    const float* W3   = (const float*)d_in[7];
    const float* b3   = (const float*)d_in[8];
    const float* W4   = (const float*)d_in[9];
    const float* b4   = (const float*)d_in[10];
    const float* eps2 = (const float*)d_in[11];
    float* out = (float*)d_out;

    // smem sizes (floats): layer1: 8192+16384+128+128+64*65+64*129 = 37248
    //                      layer2: 16384+8192+128+64+64*129+64*129 = 41280
    const size_t smem1 = 37248 * sizeof(float);
    const size_t smem2 = 41280 * sizeof(float);
    cudaFuncSetAttribute(mlp_kernel<64, 128, 128, true>,
                         cudaFuncAttributeMaxDynamicSharedMemorySize, (int)smem1);
    cudaFuncSetAttribute(mlp_kernel<128, 128, 64, false>,
                         cudaFuncAttributeMaxDynamicSharedMemorySize, (int)smem2);

    float* agg1; cudaGetSymbolAddress((void**)&agg1, g_agg1);
    float* h1;   cudaGetSymbolAddress((void**)&h1,   g_h1);
    float* agg2; cudaGetSymbolAddress((void**)&agg2, g_agg2);

    detect_kernel<<<1, 256>>>((const unsigned int*)ei);
    zero_kernel<<<1184, 256>>>();

    // layer 1: scatter x -> agg1, then MLP -> h1 (with outer relu)
    {
        long long threads = (long long)N_EDGES * (64 / 4);
        int blocks = (int)((threads + 255) / 256);
        scatter_kernel<64><<<blocks, 256>>>(x, agg1, ei);
    }
    mlp_kernel<64, 128, 128, true><<<(N_NODES + 63) / 64, 256, smem1>>>(
        x, agg1, eps1, W1, b1, W2, b2, h1);

    // layer 2: scatter h1 -> agg2, then MLP -> out (no outer relu)
    {
        long long threads = (long long)N_EDGES * (128 / 4);
        int blocks = (int)((threads + 255) / 256);
        scatter_kernel<128><<<blocks, 256>>>(h1, agg2, ei);
    }
    mlp_kernel<128, 128, 64, false><<<(N_NODES + 63) / 64, 256, smem2>>>(
        h1, agg2, eps2, W3, b3, W4, b4, out);
}

// round 3
// speedup vs baseline: 1.0439x; 1.0439x over previous
#include <cuda_runtime.h>
#include <cstddef>

#define N_NODES 50000
#define N_EDGES 800000

// ---------------- scratch (device globals: alloc-free rule) ----------------
__device__ float g_agg1[(size_t)N_NODES * 64];
__device__ float g_h1  [(size_t)N_NODES * 128];
__device__ float g_agg2[(size_t)N_NODES * 128];
__device__ int   g_is64;

// ---------------- helpers ----------------
__device__ __forceinline__ void red_add_v4(float* p, float4 v) {
    asm volatile("red.global.add.v4.f32 [%0], {%1, %2, %3, %4};"
                 :: "l"(p), "f"(v.x), "f"(v.y), "f"(v.z), "f"(v.w) : "memory");
}

// ---------------- dtype detection: int64 vs int32 edge_index ----------------
__global__ void detect_kernel(const unsigned int* __restrict__ p) {
    __shared__ int found;
    if (threadIdx.x == 0) found = 0;
    __syncthreads();
    for (int i = threadIdx.x; i < 4096; i += blockDim.x) {
        if (p[2 * i + 1] != 0u) found = 1;
    }
    __syncthreads();
    if (threadIdx.x == 0) g_is64 = found ? 0 : 1;
}

// ---------------- zero both aggregation buffers ----------------
__global__ void zero_kernel() {
    const float4 z = make_float4(0.f, 0.f, 0.f, 0.f);
    int stride = gridDim.x * blockDim.x;
    int idx = blockIdx.x * blockDim.x + threadIdx.x;
    const int n1 = N_NODES * 64 / 4;
    const int n2 = N_NODES * 128 / 4;
    float4* a1 = reinterpret_cast<float4*>(g_agg1);
    float4* a2 = reinterpret_cast<float4*>(g_agg2);
    for (int i = idx; i < n1; i += stride) a1[i] = z;
    for (int i = idx; i < n2; i += stride) a2[i] = z;
}

// ---------------- edge scatter-add (gather x[src], red-add to agg[dst]) ----
template <int C>
__global__ void __launch_bounds__(256)
scatter_kernel(const float* __restrict__ feat, float* __restrict__ agg,
               const void* __restrict__ ei) {
    const int per = C / 4;
    long long idx = (long long)blockIdx.x * blockDim.x + threadIdx.x;
    long long e  = idx / per;
    int c4 = (int)(idx % per) * 4;
    if (e >= N_EDGES) return;

    int src, dst;
    if (g_is64) {
        const long long* p = (const long long*)ei;
        src = (int)__ldg(p + e);
        dst = (int)__ldg(p + N_EDGES + e);
    } else {
        const int* p = (const int*)ei;
        src = __ldg(p + e);
        dst = __ldg(p + N_EDGES + e);
    }
    float4 v = *reinterpret_cast<const float4*>(feat + (size_t)src * C + c4);
    red_add_v4(agg + (size_t)dst * C + c4, v);
}

// ---------------- fused GIN MLP ----------------
// Block: 512 threads = 16(tx: channels) x 32(ty: nodes); NODES nodes/block.
// NPT = NODES/32 nodes per thread. Weights resident in dynamic smem.
template <int CIN, int H, int COUT, bool RELU_OUT, int NODES>
__global__ void __launch_bounds__(512)
mlp_kernel(const float* __restrict__ x, const float* __restrict__ agg,
           const float* __restrict__ epsp,
           const float* __restrict__ Wa, const float* __restrict__ ba,
           const float* __restrict__ Wb, const float* __restrict__ bb,
           float* __restrict__ out) {
    constexpr int NPT = NODES / 32;
    constexpr int MIDS = H + 4;                  // padded mid stride (16B-aligned)
    extern __shared__ float s[];
    float* Was = s;                              // CIN*H
    float* Wbs = Was + CIN * H;                  // H*COUT
    float* bas = Wbs + H * COUT;                 // H
    float* bbs = bas + H;                        // COUT
    float* ins = bbs + COUT;                     // NODES*CIN (no pad: reads are broadcast)
    float* mid = ins + NODES * CIN;              // NODES*MIDS

    const int tid = threadIdx.x;

    // cooperative weight + bias load (vectorized)
    for (int i = tid; i < CIN * H / 4; i += 512)
        reinterpret_cast<float4*>(Was)[i] = reinterpret_cast<const float4*>(Wa)[i];
    for (int i = tid; i < H * COUT / 4; i += 512)
        reinterpret_cast<float4*>(Wbs)[i] = reinterpret_cast<const float4*>(Wb)[i];
    if (tid < H) bas[tid] = ba[tid];
    else if (tid >= 128 && tid < 128 + COUT) bbs[tid - 128] = bb[tid - 128];

    const float epsf = 1.0f + __ldg(epsp);
    const int n0 = blockIdx.x * NODES;

    // ---- phase A: ins = (1+eps)*x + agg, float4 staging
    {
        constexpr int C4 = CIN / 4;
        for (int i = tid; i < NODES * C4; i += 512) {
            int n = i / C4, c4 = i - n * C4;
            int gn = n0 + n;
            float4 v = make_float4(0.f, 0.f, 0.f, 0.f);
            if (gn < N_NODES) {
                size_t g = (size_t)gn * C4 + c4;
                float4 xv = reinterpret_cast<const float4*>(x)[g];
                float4 av = reinterpret_cast<const float4*>(agg)[g];
                v.x = fmaf(epsf, xv.x, av.x);
                v.y = fmaf(epsf, xv.y, av.y);
                v.z = fmaf(epsf, xv.z, av.z);
                v.w = fmaf(epsf, xv.w, av.w);
            }
            reinterpret_cast<float4*>(ins)[n * C4 + c4] = v;
        }
    }
    __syncthreads();

    const int tx = tid & 15;
    const int ty = tid >> 4;

    // ---- phase B: mid = relu(ins @ Wa + ba); NPT nodes x 8 ch per thread
    {
        float acc[NPT][8];
        #pragma unroll
        for (int i = 0; i < NPT; i++)
            #pragma unroll
            for (int j = 0; j < 8; j++) acc[i][j] = 0.f;

        #pragma unroll 8
        for (int k = 0; k < CIN; k++) {
            float a[NPT];
            #pragma unroll
            for (int i = 0; i < NPT; i++) a[i] = ins[(ty * NPT + i) * CIN + k];
            float4 w0 = *reinterpret_cast<float4*>(&Was[k * H + tx * 8]);
            float4 w1 = *reinterpret_cast<float4*>(&Was[k * H + tx * 8 + 4]);
            float w[8] = {w0.x, w0.y, w0.z, w0.w, w1.x, w1.y, w1.z, w1.w};
            #pragma unroll
            for (int i = 0; i < NPT; i++)
                #pragma unroll
                for (int j = 0; j < 8; j++) acc[i][j] = fmaf(a[i], w[j], acc[i][j]);
        }
        #pragma unroll
        for (int i = 0; i < NPT; i++) {
            float4 v0, v1;
            v0.x = fmaxf(acc[i][0] + bas[tx * 8 + 0], 0.f);
            v0.y = fmaxf(acc[i][1] + bas[tx * 8 + 1], 0.f);
            v0.z = fmaxf(acc[i][2] + bas[tx * 8 + 2], 0.f);
            v0.w = fmaxf(acc[i][3] + bas[tx * 8 + 3], 0.f);
            v1.x = fmaxf(acc[i][4] + bas[tx * 8 + 4], 0.f);
            v1.y = fmaxf(acc[i][5] + bas[tx * 8 + 5], 0.f);
            v1.z = fmaxf(acc[i][6] + bas[tx * 8 + 6], 0.f);
            v1.w = fmaxf(acc[i][7] + bas[tx * 8 + 7], 0.f);
            float* row = &mid[(ty * NPT + i) * MIDS + tx * 8];
            reinterpret_cast<float4*>(row)[0] = v0;
            reinterpret_cast<float4*>(row)[1] = v1;
        }
    }
    __syncthreads();

    // ---- phase C: out = mid @ Wb + bb (optional relu); NPT nodes x CPT ch
    {
        constexpr int CPT = COUT / 16;
        float acc[NPT][CPT];
        #pragma unroll
        for (int i = 0; i < NPT; i++)
            #pragma unroll
            for (int j = 0; j < CPT; j++) acc[i][j] = 0.f;

        #pragma unroll 8
        for (int k = 0; k < H; k++) {
            float a[NPT];
            #pragma unroll
            for (int i = 0; i < NPT; i++) a[i] = mid[(ty * NPT + i) * MIDS + k];
            float w[CPT];
            #pragma unroll
            for (int q = 0; q < CPT / 4; q++) {
                float4 wq = *reinterpret_cast<float4*>(&Wbs[k * COUT + tx * CPT + q * 4]);
                w[q * 4 + 0] = wq.x; w[q * 4 + 1] = wq.y;
                w[q * 4 + 2] = wq.z; w[q * 4 + 3] = wq.w;
            }
            #pragma unroll
            for (int i = 0; i < NPT; i++)
                #pragma unroll
                for (int j = 0; j < CPT; j++) acc[i][j] = fmaf(a[i], w[j], acc[i][j]);
        }
        #pragma unroll
        for (int i = 0; i < NPT; i++) {
            int gn = n0 + ty * NPT + i;
            if (gn < N_NODES) {
                #pragma unroll
                for (int j = 0; j < CPT; j++) {
                    float v = acc[i][j] + bbs[tx * CPT + j];
                    if (RELU_OUT) v = v > 0.f ? v : 0.f;
                    out[(size_t)gn * COUT + tx * CPT + j] = v;
                }
            }
        }
    }
}

// ---------------- launch ----------------
extern "C" void kernel_launch(void* const* d_in, const int* in_sizes, int n_in,
                              void* d_out, int out_size) {
    const float* x    = (const float*)d_in[0];
    const void*  ei   = d_in[1];
    const float* W1   = (const float*)d_in[2];
    const float* b1   = (const float*)d_in[3];
    const float* W2   = (const float*)d_in[4];
    const float* b2   = (const float*)d_in[5];
    const float* eps1 = (const float*)d_in[6];
    const float* W3   = (const float*)d_in[7];
    const float* b3   = (const float*)d_in[8];
    const float* W4   = (const float*)d_in[9];
    const float* b4   = (const float*)d_in[10];
    const float* eps2 = (const float*)d_in[11];
    float* out = (float*)d_out;

    // layer1 smem (floats): 8192 + 16384 + 128 + 128 + 128*64 + 128*132 = 49920
    // layer2 smem (floats): 16384 + 8192 + 128 + 64 + 64*128 + 64*132 = 41408
    const size_t smem1 = 49920 * sizeof(float);
    const size_t smem2 = 41408 * sizeof(float);
    cudaFuncSetAttribute(mlp_kernel<64, 128, 128, true, 128>,
                         cudaFuncAttributeMaxDynamicSharedMemorySize, (int)smem1);
    cudaFuncSetAttribute(mlp_kernel<128, 128, 64, false, 64>,
                         cudaFuncAttributeMaxDynamicSharedMemorySize, (int)smem2);

    float* agg1; cudaGetSymbolAddress((void**)&agg1, g_agg1);
    float* h1;   cudaGetSymbolAddress((void**)&h1,   g_h1);
    float* agg2; cudaGetSymbolAddress((void**)&agg2, g_agg2);

    detect_kernel<<<1, 256>>>((const unsigned int*)ei);
    zero_kernel<<<1184, 256>>>();

    // layer 1: scatter x -> agg1, then MLP -> h1 (with outer relu)
    {
        long long threads = (long long)N_EDGES * (64 / 4);
        int blocks = (int)((threads + 255) / 256);
        scatter_kernel<64><<<blocks, 256>>>(x, agg1, ei);
    }
    mlp_kernel<64, 128, 128, true, 128><<<(N_NODES + 127) / 128, 512, smem1>>>(
        x, agg1, eps1, W1, b1, W2, b2, h1);

    // layer 2: scatter h1 -> agg2, then MLP -> out (no outer relu)
    {
        long long threads = (long long)N_EDGES * (128 / 4);
        int blocks = (int)((threads + 255) / 256);
        scatter_kernel<128><<<blocks, 256>>>(h1, agg2, ei);
    }
    mlp_kernel<128, 128, 64, false, 64><<<(N_NODES + 63) / 64, 512, smem2>>>(
        h1, agg2, eps2, W3, b3, W4, b4, out);
}